// round 8
// baseline (speedup 1.0000x reference)
#include <cuda_runtime.h>
#include <cuda_bf16.h>
#include <cstdint>

// ---------------------------------------------------------------------------
// GraphAttentionLayer: N=4096, R=4, Fin=256, Fout=64
//   Wh = h@W; Wh1 = Wh@a[:F]; Wh2 = Wh@a[F:]
//   s  = leaky_relu(Wh1_i + Wh2_j, 0.2) * A[r,i,j]   (A<=0 -> masked)
//   e  = softmax over i (axis=1)  -> column-normalized
//   h' = einsum('rij,jf->rif', e, Wh)  -> warp mma.sync bf16x2, 3 chains
//   out = [ elu(h_cat) (N x R*F) | e (R x N x N) ]
//
// R8: R7 structure with vectorized memory paths — float4 edge loads,
// float4 streaming e stores (st.global.cs), float4 stats kernel.
// ---------------------------------------------------------------------------

namespace {
constexpr int N    = 4096;
constexpr int R    = 4;
constexpr int FIN  = 256;
constexpr int F    = 64;
constexpr int SEGS = 32;
constexpr int SEGLEN = N / SEGS;     // 128
constexpr int TI   = 64;             // i-tile
constexpr int TJ   = 64;             // j chunk
constexpr int NC   = N / TJ;         // 64
constexpr float ALPHA = 0.2f;

// smem layout (bytes)
constexpr int B_STRIDE = 144;
constexpr int B_SPLIT  = F * B_STRIDE;        // 9216
constexpr int B_BUF    = 2 * B_SPLIT;         // 18432
constexpr int OFF_B    = 0;                   // 2 buffers
constexpr int OFF_WH1  = 2 * B_BUF;           // 36864 ; 64 floats
constexpr int A_STRIDE = 144;
constexpr int A_SPLIT  = TI * A_STRIDE;       // 9216
constexpr int OFF_A    = OFF_WH1 + 256;       // 37120 ; 2 splits
constexpr int SMEM_TOTAL = OFF_A + 2 * A_SPLIT;  // 55552
}

// Scratch (static device globals; no runtime allocation)
__device__ __align__(16) float g_Wh[N * F];                 // 1 MB
__device__ __align__(16) __nv_bfloat16 g_WhT[2][F][N];      // 1 MB
__device__ float g_Wh1[N];
__device__ float g_Wh2[N];
__device__ __align__(16) float g_pl[R * SEGS * N];
__device__ __align__(16) float g_linv[R * N];

// ---------------------------------------------------------------------------
// PTX helpers
// ---------------------------------------------------------------------------
__device__ __forceinline__ uint32_t smem_u32(const void* p) {
    return (uint32_t)__cvta_generic_to_shared(p);
}
__device__ __forceinline__ void cp16(uint32_t dst, const void* src) {
    asm volatile("cp.async.cg.shared.global [%0], [%1], 16;" :: "r"(dst), "l"(src));
}
__device__ __forceinline__ void cp_commit() {
    asm volatile("cp.async.commit_group;");
}
template <int NG>
__device__ __forceinline__ void cp_wait() {
    asm volatile("cp.async.wait_group %0;" :: "n"(NG));
}
__device__ __forceinline__ void ldm4(uint32_t& d0, uint32_t& d1, uint32_t& d2,
                                     uint32_t& d3, uint32_t addr) {
    asm volatile("ldmatrix.sync.aligned.m8n8.x4.shared.b16 {%0,%1,%2,%3}, [%4];"
                 : "=r"(d0), "=r"(d1), "=r"(d2), "=r"(d3) : "r"(addr));
}
__device__ __forceinline__ void mma16816(float* c, const uint32_t* a,
                                         uint32_t b0, uint32_t b1) {
    asm volatile(
        "mma.sync.aligned.m16n8k16.row.col.f32.bf16.bf16.f32 "
        "{%0,%1,%2,%3}, {%4,%5,%6,%7}, {%8,%9}, {%0,%1,%2,%3};"
        : "+f"(c[0]), "+f"(c[1]), "+f"(c[2]), "+f"(c[3])
        : "r"(a[0]), "r"(a[1]), "r"(a[2]), "r"(a[3]), "r"(b0), "r"(b1));
}
__device__ __forceinline__ void sts_v2(uint32_t addr, uint32_t u0, uint32_t u1) {
    asm volatile("st.shared.v2.b32 [%0], {%1, %2};" :: "r"(addr), "r"(u0), "r"(u1));
}

// ---------------------------------------------------------------------------
// Kernel 1: Wh [N,F], Wh1[N], Wh2[N].  grid = N blocks x 64 threads.
// ---------------------------------------------------------------------------
__global__ __launch_bounds__(64) void k_wh(const float* __restrict__ h,
                                           const float* __restrict__ W,
                                           const float* __restrict__ a) {
    __shared__ float hs[FIN];
    __shared__ float red[4];
    const int i = blockIdx.x;
    const int f = threadIdx.x;

    #pragma unroll
    for (int k = f; k < FIN; k += 64) hs[k] = h[(size_t)i * FIN + k];
    __syncthreads();

    float acc = 0.f;
    #pragma unroll 8
    for (int k = 0; k < FIN; k++) acc = fmaf(hs[k], W[k * F + f], acc);
    g_Wh[(size_t)i * F + f] = acc;

    float v1 = acc * a[f];
    float v2 = acc * a[F + f];
    #pragma unroll
    for (int off = 16; off; off >>= 1) {
        v1 += __shfl_down_sync(0xffffffffu, v1, off);
        v2 += __shfl_down_sync(0xffffffffu, v2, off);
    }
    if ((f & 31) == 0) { red[f >> 5] = v1; red[2 + (f >> 5)] = v2; }
    __syncthreads();
    if (f == 0) {
        g_Wh1[i] = red[0] + red[1];
        g_Wh2[i] = red[2] + red[3];
    }
}

// ---------------------------------------------------------------------------
// Kernel 1b: transpose + bf16x2 split of Wh -> g_WhT[s][f][j].
// ---------------------------------------------------------------------------
__global__ __launch_bounds__(256) void k_split() {
    __shared__ float sT[F][64 + 1];
    const int i0 = blockIdx.x * 64;
    const int t = threadIdx.x;

    for (int idx = t; idx < 64 * F; idx += 256) {
        const int i = idx >> 6;
        const int f = idx & 63;
        sT[f][i] = g_Wh[(size_t)(i0 + i) * F + f];
    }
    __syncthreads();
    for (int idx = t; idx < 64 * F; idx += 256) {
        const int f  = idx >> 6;
        const int ii = idx & 63;
        const float w = sT[f][ii];
        const __nv_bfloat16 b0 = __float2bfloat16(w);
        const __nv_bfloat16 b1 = __float2bfloat16(w - __bfloat162float(b0));
        g_WhT[0][f][i0 + ii] = b0;
        g_WhT[1][f][i0 + ii] = b1;
    }
}

// ---------------------------------------------------------------------------
// Kernel 2a: partial column sum-exp, float4 per thread.
// grid = (N/1024, SEGS, R) = (4, 32, 4) = 512 blocks, 256 threads.
// ---------------------------------------------------------------------------
__global__ __launch_bounds__(256) void k_stats_part(const float* __restrict__ edge) {
    __shared__ float swh1[SEGLEN];
    const int t   = threadIdx.x;
    const int j   = blockIdx.x * 1024 + 4 * t;
    const int seg = blockIdx.y;
    const int r   = blockIdx.z;
    const int i0  = seg * SEGLEN;

    if (t < SEGLEN) swh1[t] = g_Wh1[i0 + t];
    __syncthreads();

    const float4 w2 = *(const float4*)(g_Wh2 + j);
    const float* base = edge + (size_t)r * N * N + (size_t)i0 * N + j;

    float lx = 0.f, ly = 0.f, lz = 0.f, lw = 0.f;
    #pragma unroll 4
    for (int k = 0; k < SEGLEN; k++) {
        const float4 a = __ldg((const float4*)(base + (size_t)k * N));
        const float xr = swh1[k];
        float x, lr;
        x = xr + w2.x; lr = fmaxf(x, ALPHA * x);
        lx += (a.x > 0.f) ? __expf(lr * a.x) : 0.f;
        x = xr + w2.y; lr = fmaxf(x, ALPHA * x);
        ly += (a.y > 0.f) ? __expf(lr * a.y) : 0.f;
        x = xr + w2.z; lr = fmaxf(x, ALPHA * x);
        lz += (a.z > 0.f) ? __expf(lr * a.z) : 0.f;
        x = xr + w2.w; lr = fmaxf(x, ALPHA * x);
        lw += (a.w > 0.f) ? __expf(lr * a.w) : 0.f;
    }
    float4 out;
    out.x = lx; out.y = ly; out.z = lz; out.w = lw;
    *(float4*)(g_pl + ((size_t)r * SEGS + seg) * N + j) = out;
}

// ---------------------------------------------------------------------------
// Kernel 2b: merge -> g_linv.  grid = R*N/1024 = 16 blocks x 256 threads.
// ---------------------------------------------------------------------------
__global__ __launch_bounds__(256) void k_stats_final() {
    const int idx = blockIdx.x * 256 + threadIdx.x;   // 0..4095
    const int r = idx >> 10;
    const int j = (idx & 1023) * 4;

    float lx = 0.f, ly = 0.f, lz = 0.f, lw = 0.f;
    #pragma unroll
    for (int s = 0; s < SEGS; s++) {
        const float4 p = *(const float4*)(g_pl + ((size_t)r * SEGS + s) * N + j);
        lx += p.x; ly += p.y; lz += p.z; lw += p.w;
    }
    float4 inv;
    inv.x = 1.f / lx; inv.y = 1.f / ly; inv.z = 1.f / lz; inv.w = 1.f / lw;
    *(float4*)(g_linv + (size_t)r * N + j) = inv;
}

// ---------------------------------------------------------------------------
// Kernel 3 (fused): per (r, 64-row tile), all 64 j-chunks.
// Warp w: m-group = w>>1 (16 rows), n-half = w&1 (32 of 64 f-cols).
// Transform: lane owns 4 consecutive cols (float4 LDG / STG.cs), 2 rows/iter.
// grid = (N/TI, R) = (64, 4) = 256 blocks, 256 threads, 2 blocks/SM.
// ---------------------------------------------------------------------------
__global__ __launch_bounds__(256, 2) void k_fused(const float* __restrict__ edge,
                                                  float* __restrict__ out1,
                                                  float* __restrict__ outE) {
    extern __shared__ __align__(128) char smc[];
    const uint32_t smb = smem_u32(smc);
    float* sWh1 = (float*)(smc + OFF_WH1);

    const int t    = threadIdx.x;
    const int wid  = t >> 5;
    const int lane = t & 31;
    const int mg   = wid >> 1;        // 0..3 m-group (16 rows)
    const int nh   = wid & 1;         // 0..1 n-half (32 cols)
    const int cl   = lane & 15;       // col group (4 floats)
    const int rh   = lane >> 4;       // row offset within pair
    const int r    = blockIdx.y;
    const int i0   = blockIdx.x * TI;
    const size_t ebase = (size_t)r * N * N;
    const bool writeE = (outE != nullptr);

    if (t < TI) sWh1[t] = g_Wh1[i0 + t];
    __syncthreads();

    const int trow = 16 * mg + 8 * nh;    // transform row base (8 rows)
    float wh1v[8];
    #pragma unroll
    for (int k = 0; k < 8; k++) wh1v[k] = sWh1[trow + k];

    // ldmatrix lane address bases (constant over chunks)
    const uint32_t aBase = smb + OFF_A;
    const uint32_t aLd = aBase +
        (uint32_t)((16 * mg + (lane & 7) + 8 * ((lane >> 3) & 1)) * A_STRIDE +
                   (lane >> 4) * 16);
    const uint32_t bLBase = smb + OFF_B +
        (uint32_t)(((lane & 7) + 8 * (lane >> 4)) * B_STRIDE +
                   ((lane >> 3) & 1) * 16);

    auto issue_cpB = [&](int jc) {
        const int buf = jc & 1;
        const int j0 = jc * TJ;
        const uint32_t bBase = smb + OFF_B + buf * B_BUF;
        #pragma unroll
        for (int g = 0; g < 4; g++) {
            const int idx = g * 256 + t;        // 0..1023
            const int s   = idx >> 9;           // split
            const int rem = idx & 511;
            const int row = rem >> 3;           // f row
            const int c16 = rem & 7;
            cp16(bBase + s * B_SPLIT + (uint32_t)(row * B_STRIDE + c16 * 16),
                 &g_WhT[s][row][j0 + c16 * 8]);
        }
        cp_commit();
    };
    // raw rows: iteration k covers rows trow+2k+rh, cols j0+4*cl..+3
    auto issue_raw = [&](int jc, float4 (&raw)[4]) {
        const int j0 = jc * TJ;
        const float* base = edge + ebase + (size_t)(i0 + trow + rh) * N + j0 + 4 * cl;
        #pragma unroll
        for (int k = 0; k < 4; k++)
            raw[k] = __ldg((const float4*)(base + (size_t)(2 * k) * N));
    };

    float c[4][4];
    #pragma unroll
    for (int ng = 0; ng < 4; ng++)
        #pragma unroll
        for (int u = 0; u < 4; u++) c[ng][u] = 0.f;

    auto step = [&](int jc, float4 (&cur)[4], float4 (&nxt)[4],
                    float4& lnvC, float4& lnvN, float4& w2C, float4& w2N) {
        const int j0 = jc * TJ;
        const bool more = (jc + 1 < NC);
        if (more) {
            issue_cpB(jc + 1);
            issue_raw(jc + 1, nxt);
            lnvN = __ldg((const float4*)(g_linv + r * N + j0 + TJ + 4 * cl));
            w2N  = __ldg((const float4*)(g_Wh2 + j0 + TJ + 4 * cl));
        }

        // ---- transform: raw -> e (gmem, streaming) + bf16x2 A splits ----
        #pragma unroll
        for (int k = 0; k < 4; k++) {
            const int row = trow + 2 * k + rh;
            const float wh1 = wh1v[2 * k + rh];
            const float4 av = cur[k];
            float4 ev;
            {
                const float x = wh1 + w2C.x, lr = fmaxf(x, ALPHA * x);
                ev.x = (av.x > 0.f) ? __expf(lr * av.x) * lnvC.x : 0.f;
            }
            {
                const float x = wh1 + w2C.y, lr = fmaxf(x, ALPHA * x);
                ev.y = (av.y > 0.f) ? __expf(lr * av.y) * lnvC.y : 0.f;
            }
            {
                const float x = wh1 + w2C.z, lr = fmaxf(x, ALPHA * x);
                ev.z = (av.z > 0.f) ? __expf(lr * av.z) * lnvC.z : 0.f;
            }
            {
                const float x = wh1 + w2C.w, lr = fmaxf(x, ALPHA * x);
                ev.w = (av.w > 0.f) ? __expf(lr * av.w) * lnvC.w : 0.f;
            }
            if (writeE)
                __stcs((float4*)(outE + ebase + (size_t)(i0 + row) * N + j0 + 4 * cl),
                       ev);

            // bf16x2 splits: cols (4cl, 4cl+1) and (4cl+2, 4cl+3)
            const __nv_bfloat162 h01 = __floats2bfloat162_rn(ev.x, ev.y);
            const __nv_bfloat162 h23 = __floats2bfloat162_rn(ev.z, ev.w);
            const __nv_bfloat162 l01 = __floats2bfloat162_rn(
                ev.x - __bfloat162float(h01.x), ev.y - __bfloat162float(h01.y));
            const __nv_bfloat162 l23 = __floats2bfloat162_rn(
                ev.z - __bfloat162float(h23.x), ev.w - __bfloat162float(h23.y));
            const uint32_t so = (uint32_t)(row * A_STRIDE + cl * 8);
            sts_v2(aBase + so, *(const uint32_t*)&h01, *(const uint32_t*)&h23);
            sts_v2(aBase + A_SPLIT + so, *(const uint32_t*)&l01,
                   *(const uint32_t*)&l23);
        }

        if (more) cp_wait<1>(); else cp_wait<0>();
        __syncthreads();

        // ---- MMA: 4 k-steps x 2 n16-groups (this warp's half) x 3 chains ----
        const uint32_t bBuf = bLBase + (jc & 1) * B_BUF;
        #pragma unroll
        for (int ks = 0; ks < 4; ks++) {
            uint32_t a0[4], a1[4];
            ldm4(a0[0], a0[1], a0[2], a0[3], aLd + ks * 32);
            ldm4(a1[0], a1[1], a1[2], a1[3], aLd + A_SPLIT + ks * 32);
            #pragma unroll
            for (int u = 0; u < 2; u++) {
                const int ng2 = 2 * nh + u;
                const uint32_t bo = bBuf + (uint32_t)(ng2 * 16 * B_STRIDE + ks * 32);
                uint32_t b00, b01, b02, b03, b10, b11, b12, b13;
                ldm4(b00, b01, b02, b03, bo);
                ldm4(b10, b11, b12, b13, bo + B_SPLIT);
                mma16816(c[2 * u], a0, b00, b01);
                mma16816(c[2 * u], a0, b10, b11);
                mma16816(c[2 * u], a1, b00, b01);
                mma16816(c[2 * u + 1], a0, b02, b03);
                mma16816(c[2 * u + 1], a0, b12, b13);
                mma16816(c[2 * u + 1], a1, b02, b03);
            }
        }
        __syncthreads();

        lnvC = lnvN; w2C = w2N;
    };

    // ---- pipeline ----
    float4 rawP[4], rawQ[4];
    float4 lnvC, lnvN, w2C, w2N;
    issue_cpB(0);
    issue_raw(0, rawP);
    lnvC = __ldg((const float4*)(g_linv + r * N + 4 * cl));
    w2C  = __ldg((const float4*)(g_Wh2 + 4 * cl));
    lnvN = lnvC; w2N = w2C;

    for (int jc = 0; jc < NC; jc += 2) {
        step(jc, rawP, rawQ, lnvC, lnvN, w2C, w2N);
        step(jc + 1, rawQ, rawP, lnvC, lnvN, w2C, w2N);
    }

    // ---- epilogue: elu + store out1[i, r*F + f] ----
    if (out1 != nullptr) {
        const int rlo = i0 + 16 * mg + (lane >> 2);
        const int rhi = rlo + 8;
        #pragma unroll
        for (int u = 0; u < 2; u++) {
            const int ng2 = 2 * nh + u;
            #pragma unroll
            for (int v = 0; v < 2; v++) {
                const int f0 = 8 * (2 * ng2 + v) + 2 * (lane & 3);
                const float* cc = c[2 * u + v];
                float2 o;
                o.x = (cc[0] > 0.f) ? cc[0] : expm1f(cc[0]);
                o.y = (cc[1] > 0.f) ? cc[1] : expm1f(cc[1]);
                *(float2*)(out1 + (size_t)rlo * (R * F) + r * F + f0) = o;
                o.x = (cc[2] > 0.f) ? cc[2] : expm1f(cc[2]);
                o.y = (cc[3] > 0.f) ? cc[3] : expm1f(cc[3]);
                *(float2*)(out1 + (size_t)rhi * (R * F) + r * F + f0) = o;
            }
        }
    }
}

// ---------------------------------------------------------------------------
extern "C" void kernel_launch(void* const* d_in, const int* in_sizes, int n_in,
                              void* d_out, int out_size) {
    const float* h    = (const float*)d_in[0];
    const float* edge = (const float*)d_in[1];
    const float* W    = (const float*)d_in[2];
    const float* a    = (const float*)d_in[3];
    float* out = (float*)d_out;

    const long long size1 = (long long)N * R * F;   // 1,048,576
    const long long sizeE = (long long)R * N * N;   // 67,108,864

    float* out1 = nullptr;
    float* outE = nullptr;
    if ((long long)out_size >= size1 + sizeE) {
        out1 = out;
        outE = out + size1;
    } else if ((long long)out_size >= sizeE) {
        outE = out;
    } else {
        out1 = out;
    }

    cudaFuncSetAttribute(k_fused, cudaFuncAttributeMaxDynamicSharedMemorySize,
                         SMEM_TOTAL);

    k_wh<<<N, 64>>>(h, W, a);
    k_split<<<N / 64, 256>>>();

    dim3 g2(N / 1024, SEGS, R);
    k_stats_part<<<g2, 256>>>(edge);
    k_stats_final<<<(R * N) / 1024, 256>>>();

    dim3 g3(N / TI, R);
    k_fused<<<g3, 256, SMEM_TOTAL>>>(edge, out1, outE);
}

// round 9
// speedup vs baseline: 1.0331x; 1.0331x over previous
#include <cuda_runtime.h>
#include <cuda_bf16.h>
#include <cstdint>

// ---------------------------------------------------------------------------
// GraphAttentionLayer: N=4096, R=4, Fin=256, Fout=64
//   Wh = h@W; Wh1 = Wh@a[:F]; Wh2 = Wh@a[F:]
//   s  = leaky_relu(Wh1_i + Wh2_j, 0.2) * A[r,i,j]   (A<=0 -> masked)
//   e  = softmax over i (axis=1)  -> column-normalized
//   h' = einsum('rij,jf->rif', e, Wh)  -> warp mma.sync bf16x2, 3 chains
//   out = [ elu(h_cat) (N x R*F) | e (R x N x N) ]
//
// R9: R8 structure with reduced synchronization — one block barrier per
// chunk (B buffer handoff) + one 64-thread named pair barrier (A halves),
// no trailing barrier. Raw LDGs issued before the cp_wait stall point.
// ---------------------------------------------------------------------------

namespace {
constexpr int N    = 4096;
constexpr int R    = 4;
constexpr int FIN  = 256;
constexpr int F    = 64;
constexpr int SEGS = 32;
constexpr int SEGLEN = N / SEGS;     // 128
constexpr int TI   = 64;             // i-tile
constexpr int TJ   = 64;             // j chunk
constexpr int NC   = N / TJ;         // 64
constexpr float ALPHA = 0.2f;

// smem layout (bytes)
constexpr int B_STRIDE = 144;
constexpr int B_SPLIT  = F * B_STRIDE;        // 9216
constexpr int B_BUF    = 2 * B_SPLIT;         // 18432
constexpr int OFF_B    = 0;                   // 2 buffers
constexpr int OFF_WH1  = 2 * B_BUF;           // 36864 ; 64 floats
constexpr int A_STRIDE = 144;
constexpr int A_SPLIT  = TI * A_STRIDE;       // 9216
constexpr int OFF_A    = OFF_WH1 + 256;       // 37120 ; 2 splits
constexpr int SMEM_TOTAL = OFF_A + 2 * A_SPLIT;  // 55552
}

// Scratch (static device globals; no runtime allocation)
__device__ __align__(16) float g_Wh[N * F];                 // 1 MB
__device__ __align__(16) __nv_bfloat16 g_WhT[2][F][N];      // 1 MB
__device__ float g_Wh1[N];
__device__ float g_Wh2[N];
__device__ __align__(16) float g_pl[R * SEGS * N];
__device__ __align__(16) float g_linv[R * N];

// ---------------------------------------------------------------------------
// PTX helpers
// ---------------------------------------------------------------------------
__device__ __forceinline__ uint32_t smem_u32(const void* p) {
    return (uint32_t)__cvta_generic_to_shared(p);
}
__device__ __forceinline__ void cp16(uint32_t dst, const void* src) {
    asm volatile("cp.async.cg.shared.global [%0], [%1], 16;" :: "r"(dst), "l"(src));
}
__device__ __forceinline__ void cp_commit() {
    asm volatile("cp.async.commit_group;");
}
template <int NG>
__device__ __forceinline__ void cp_wait() {
    asm volatile("cp.async.wait_group %0;" :: "n"(NG));
}
__device__ __forceinline__ void bar_pair(int id) {
    asm volatile("bar.sync %0, 64;" :: "r"(id) : "memory");
}
__device__ __forceinline__ void ldm4(uint32_t& d0, uint32_t& d1, uint32_t& d2,
                                     uint32_t& d3, uint32_t addr) {
    asm volatile("ldmatrix.sync.aligned.m8n8.x4.shared.b16 {%0,%1,%2,%3}, [%4];"
                 : "=r"(d0), "=r"(d1), "=r"(d2), "=r"(d3) : "r"(addr));
}
__device__ __forceinline__ void mma16816(float* c, const uint32_t* a,
                                         uint32_t b0, uint32_t b1) {
    asm volatile(
        "mma.sync.aligned.m16n8k16.row.col.f32.bf16.bf16.f32 "
        "{%0,%1,%2,%3}, {%4,%5,%6,%7}, {%8,%9}, {%0,%1,%2,%3};"
        : "+f"(c[0]), "+f"(c[1]), "+f"(c[2]), "+f"(c[3])
        : "r"(a[0]), "r"(a[1]), "r"(a[2]), "r"(a[3]), "r"(b0), "r"(b1));
}
__device__ __forceinline__ void sts_v2(uint32_t addr, uint32_t u0, uint32_t u1) {
    asm volatile("st.shared.v2.b32 [%0], {%1, %2};" :: "r"(addr), "r"(u0), "r"(u1));
}

// ---------------------------------------------------------------------------
// Kernel 1: Wh [N,F], Wh1[N], Wh2[N].  grid = N blocks x 64 threads.
// ---------------------------------------------------------------------------
__global__ __launch_bounds__(64) void k_wh(const float* __restrict__ h,
                                           const float* __restrict__ W,
                                           const float* __restrict__ a) {
    __shared__ float hs[FIN];
    __shared__ float red[4];
    const int i = blockIdx.x;
    const int f = threadIdx.x;

    #pragma unroll
    for (int k = f; k < FIN; k += 64) hs[k] = h[(size_t)i * FIN + k];
    __syncthreads();

    float acc = 0.f;
    #pragma unroll 8
    for (int k = 0; k < FIN; k++) acc = fmaf(hs[k], W[k * F + f], acc);
    g_Wh[(size_t)i * F + f] = acc;

    float v1 = acc * a[f];
    float v2 = acc * a[F + f];
    #pragma unroll
    for (int off = 16; off; off >>= 1) {
        v1 += __shfl_down_sync(0xffffffffu, v1, off);
        v2 += __shfl_down_sync(0xffffffffu, v2, off);
    }
    if ((f & 31) == 0) { red[f >> 5] = v1; red[2 + (f >> 5)] = v2; }
    __syncthreads();
    if (f == 0) {
        g_Wh1[i] = red[0] + red[1];
        g_Wh2[i] = red[2] + red[3];
    }
}

// ---------------------------------------------------------------------------
// Kernel 1b: transpose + bf16x2 split of Wh -> g_WhT[s][f][j].
// ---------------------------------------------------------------------------
__global__ __launch_bounds__(256) void k_split() {
    __shared__ float sT[F][64 + 1];
    const int i0 = blockIdx.x * 64;
    const int t = threadIdx.x;

    for (int idx = t; idx < 64 * F; idx += 256) {
        const int i = idx >> 6;
        const int f = idx & 63;
        sT[f][i] = g_Wh[(size_t)(i0 + i) * F + f];
    }
    __syncthreads();
    for (int idx = t; idx < 64 * F; idx += 256) {
        const int f  = idx >> 6;
        const int ii = idx & 63;
        const float w = sT[f][ii];
        const __nv_bfloat16 b0 = __float2bfloat16(w);
        const __nv_bfloat16 b1 = __float2bfloat16(w - __bfloat162float(b0));
        g_WhT[0][f][i0 + ii] = b0;
        g_WhT[1][f][i0 + ii] = b1;
    }
}

// ---------------------------------------------------------------------------
// Kernel 2a: partial column sum-exp, float4 per thread.
// grid = (N/1024, SEGS, R) = (4, 32, 4) = 512 blocks, 256 threads.
// ---------------------------------------------------------------------------
__global__ __launch_bounds__(256) void k_stats_part(const float* __restrict__ edge) {
    __shared__ float swh1[SEGLEN];
    const int t   = threadIdx.x;
    const int j   = blockIdx.x * 1024 + 4 * t;
    const int seg = blockIdx.y;
    const int r   = blockIdx.z;
    const int i0  = seg * SEGLEN;

    if (t < SEGLEN) swh1[t] = g_Wh1[i0 + t];
    __syncthreads();

    const float4 w2 = *(const float4*)(g_Wh2 + j);
    const float* base = edge + (size_t)r * N * N + (size_t)i0 * N + j;

    float lx = 0.f, ly = 0.f, lz = 0.f, lw = 0.f;
    #pragma unroll 4
    for (int k = 0; k < SEGLEN; k++) {
        const float4 a = __ldg((const float4*)(base + (size_t)k * N));
        const float xr = swh1[k];
        float x, lr;
        x = xr + w2.x; lr = fmaxf(x, ALPHA * x);
        lx += (a.x > 0.f) ? __expf(lr * a.x) : 0.f;
        x = xr + w2.y; lr = fmaxf(x, ALPHA * x);
        ly += (a.y > 0.f) ? __expf(lr * a.y) : 0.f;
        x = xr + w2.z; lr = fmaxf(x, ALPHA * x);
        lz += (a.z > 0.f) ? __expf(lr * a.z) : 0.f;
        x = xr + w2.w; lr = fmaxf(x, ALPHA * x);
        lw += (a.w > 0.f) ? __expf(lr * a.w) : 0.f;
    }
    float4 out;
    out.x = lx; out.y = ly; out.z = lz; out.w = lw;
    *(float4*)(g_pl + ((size_t)r * SEGS + seg) * N + j) = out;
}

// ---------------------------------------------------------------------------
// Kernel 2b: merge -> g_linv.  grid = R*N/256 = 64 blocks x 256 threads.
// ---------------------------------------------------------------------------
__global__ __launch_bounds__(256) void k_stats_final() {
    const int idx = blockIdx.x * 256 + threadIdx.x;   // r*N + j
    const int r = idx >> 12;
    const int j = idx & (N - 1);
    float L = 0.f;
    #pragma unroll
    for (int s = 0; s < SEGS; s++) L += g_pl[((size_t)r * SEGS + s) * N + j];
    g_linv[idx] = 1.f / L;
}

// ---------------------------------------------------------------------------
// Kernel 3 (fused): per (r, 64-row tile), all 64 j-chunks.
// Warp w: m-group = w>>1 (16 rows), n-half = w&1 (32 of 64 f-cols).
// Per chunk: ONE block barrier (B handoff) + ONE 64-thr pair barrier (A).
// grid = (N/TI, R) = (64, 4) = 256 blocks, 256 threads, 2 blocks/SM.
// ---------------------------------------------------------------------------
__global__ __launch_bounds__(256, 2) void k_fused(const float* __restrict__ edge,
                                                  float* __restrict__ out1,
                                                  float* __restrict__ outE) {
    extern __shared__ __align__(128) char smc[];
    const uint32_t smb = smem_u32(smc);
    float* sWh1 = (float*)(smc + OFF_WH1);

    const int t    = threadIdx.x;
    const int wid  = t >> 5;
    const int lane = t & 31;
    const int mg   = wid >> 1;        // 0..3 m-group (16 rows)
    const int nh   = wid & 1;         // 0..1 n-half (32 cols)
    const int cl   = lane & 15;       // col group (4 floats)
    const int rh   = lane >> 4;       // row offset within pair
    const int r    = blockIdx.y;
    const int i0   = blockIdx.x * TI;
    const size_t ebase = (size_t)r * N * N;
    const bool writeE = (outE != nullptr);

    if (t < TI) sWh1[t] = g_Wh1[i0 + t];
    __syncthreads();

    const int trow = 16 * mg + 8 * nh;    // transform row base (8 rows)
    float wh1v[8];
    #pragma unroll
    for (int k = 0; k < 8; k++) wh1v[k] = sWh1[trow + k];

    // ldmatrix lane address bases (constant over chunks)
    const uint32_t aBase = smb + OFF_A;
    const uint32_t aLd = aBase +
        (uint32_t)((16 * mg + (lane & 7) + 8 * ((lane >> 3) & 1)) * A_STRIDE +
                   (lane >> 4) * 16);
    const uint32_t bLBase = smb + OFF_B +
        (uint32_t)(((lane & 7) + 8 * (lane >> 4)) * B_STRIDE +
                   ((lane >> 3) & 1) * 16);

    auto issue_cpB = [&](int jc) {
        const int buf = jc & 1;
        const int j0 = jc * TJ;
        const uint32_t bBase = smb + OFF_B + buf * B_BUF;
        #pragma unroll
        for (int g = 0; g < 4; g++) {
            const int idx = g * 256 + t;        // 0..1023
            const int s   = idx >> 9;           // split
            const int rem = idx & 511;
            const int row = rem >> 3;           // f row
            const int c16 = rem & 7;
            cp16(bBase + s * B_SPLIT + (uint32_t)(row * B_STRIDE + c16 * 16),
                 &g_WhT[s][row][j0 + c16 * 8]);
        }
        cp_commit();
    };
    // raw rows: iteration k covers rows trow+2k+rh, cols j0+4*cl..+3
    auto issue_raw = [&](int jc, float4 (&raw)[4]) {
        const int j0 = jc * TJ;
        const float* base = edge + ebase + (size_t)(i0 + trow + rh) * N + j0 + 4 * cl;
        #pragma unroll
        for (int k = 0; k < 4; k++)
            raw[k] = __ldg((const float4*)(base + (size_t)(2 * k) * N));
    };

    float c[4][4];
    #pragma unroll
    for (int ng = 0; ng < 4; ng++)
        #pragma unroll
        for (int u = 0; u < 4; u++) c[ng][u] = 0.f;

    auto step = [&](int jc, float4 (&cur)[4], float4 (&nxt)[4],
                    float4& lnvC, float4& lnvN, float4& w2C, float4& w2N) {
        const int j0 = jc * TJ;
        const bool more = (jc + 1 < NC);
        // issue raw LDGs before the wait point so they overlap the stall
        if (more) {
            issue_raw(jc + 1, nxt);
            lnvN = __ldg((const float4*)(g_linv + r * N + j0 + TJ + 4 * cl));
            w2N  = __ldg((const float4*)(g_Wh2 + j0 + TJ + 4 * cl));
        }

        cp_wait<0>();          // B(jc) landed (issued last step)
        __syncthreads();       // B(jc) visible; all warps' MMA(jc-1) done
        if (more) issue_cpB(jc + 1);   // overwrites buf (jc-1)&1 — now safe

        // ---- transform: raw -> e (gmem, streaming) + bf16x2 A splits ----
        #pragma unroll
        for (int k = 0; k < 4; k++) {
            const int row = trow + 2 * k + rh;
            const float wh1 = wh1v[2 * k + rh];
            const float4 av = cur[k];
            float4 ev;
            {
                const float x = wh1 + w2C.x, lr = fmaxf(x, ALPHA * x);
                ev.x = (av.x > 0.f) ? __expf(lr * av.x) * lnvC.x : 0.f;
            }
            {
                const float x = wh1 + w2C.y, lr = fmaxf(x, ALPHA * x);
                ev.y = (av.y > 0.f) ? __expf(lr * av.y) * lnvC.y : 0.f;
            }
            {
                const float x = wh1 + w2C.z, lr = fmaxf(x, ALPHA * x);
                ev.z = (av.z > 0.f) ? __expf(lr * av.z) * lnvC.z : 0.f;
            }
            {
                const float x = wh1 + w2C.w, lr = fmaxf(x, ALPHA * x);
                ev.w = (av.w > 0.f) ? __expf(lr * av.w) * lnvC.w : 0.f;
            }
            if (writeE)
                __stcs((float4*)(outE + ebase + (size_t)(i0 + row) * N + j0 + 4 * cl),
                       ev);

            // bf16x2 splits: cols (4cl, 4cl+1) and (4cl+2, 4cl+3)
            const __nv_bfloat162 h01 = __floats2bfloat162_rn(ev.x, ev.y);
            const __nv_bfloat162 h23 = __floats2bfloat162_rn(ev.z, ev.w);
            const __nv_bfloat162 l01 = __floats2bfloat162_rn(
                ev.x - __bfloat162float(h01.x), ev.y - __bfloat162float(h01.y));
            const __nv_bfloat162 l23 = __floats2bfloat162_rn(
                ev.z - __bfloat162float(h23.x), ev.w - __bfloat162float(h23.y));
            const uint32_t so = (uint32_t)(row * A_STRIDE + cl * 8);
            sts_v2(aBase + so, *(const uint32_t*)&h01, *(const uint32_t*)&h23);
            sts_v2(aBase + A_SPLIT + so, *(const uint32_t*)&l01,
                   *(const uint32_t*)&l23);
        }

        // pair barrier: partner's 8 A-rows visible (64 threads, id = mg+1)
        bar_pair(mg + 1);

        // ---- MMA: 4 k-steps x 2 n16-groups (this warp's half) x 3 chains ----
        const uint32_t bBuf = bLBase + (jc & 1) * B_BUF;
        #pragma unroll
        for (int ks = 0; ks < 4; ks++) {
            uint32_t a0[4], a1[4];
            ldm4(a0[0], a0[1], a0[2], a0[3], aLd + ks * 32);
            ldm4(a1[0], a1[1], a1[2], a1[3], aLd + A_SPLIT + ks * 32);
            #pragma unroll
            for (int u = 0; u < 2; u++) {
                const int ng2 = 2 * nh + u;
                const uint32_t bo = bBuf + (uint32_t)(ng2 * 16 * B_STRIDE + ks * 32);
                uint32_t b00, b01, b02, b03, b10, b11, b12, b13;
                ldm4(b00, b01, b02, b03, bo);
                ldm4(b10, b11, b12, b13, bo + B_SPLIT);
                mma16816(c[2 * u], a0, b00, b01);
                mma16816(c[2 * u], a0, b10, b11);
                mma16816(c[2 * u], a1, b00, b01);
                mma16816(c[2 * u + 1], a0, b02, b03);
                mma16816(c[2 * u + 1], a0, b12, b13);
                mma16816(c[2 * u + 1], a1, b02, b03);
            }
        }
        // no trailing barrier: next step's __syncthreads protects A and B buf

        lnvC = lnvN; w2C = w2N;
    };

    // ---- pipeline ----
    float4 rawP[4], rawQ[4];
    float4 lnvC, lnvN, w2C, w2N;
    issue_cpB(0);
    issue_raw(0, rawP);
    lnvC = __ldg((const float4*)(g_linv + r * N + 4 * cl));
    w2C  = __ldg((const float4*)(g_Wh2 + 4 * cl));
    lnvN = lnvC; w2N = w2C;

    for (int jc = 0; jc < NC; jc += 2) {
        step(jc, rawP, rawQ, lnvC, lnvN, w2C, w2N);
        step(jc + 1, rawQ, rawP, lnvC, lnvN, w2C, w2N);
    }

    // ---- epilogue: elu + store out1[i, r*F + f] ----
    if (out1 != nullptr) {
        const int rlo = i0 + 16 * mg + (lane >> 2);
        const int rhi = rlo + 8;
        #pragma unroll
        for (int u = 0; u < 2; u++) {
            const int ng2 = 2 * nh + u;
            #pragma unroll
            for (int v = 0; v < 2; v++) {
                const int f0 = 8 * (2 * ng2 + v) + 2 * (lane & 3);
                const float* cc = c[2 * u + v];
                float2 o;
                o.x = (cc[0] > 0.f) ? cc[0] : expm1f(cc[0]);
                o.y = (cc[1] > 0.f) ? cc[1] : expm1f(cc[1]);
                *(float2*)(out1 + (size_t)rlo * (R * F) + r * F + f0) = o;
                o.x = (cc[2] > 0.f) ? cc[2] : expm1f(cc[2]);
                o.y = (cc[3] > 0.f) ? cc[3] : expm1f(cc[3]);
                *(float2*)(out1 + (size_t)rhi * (R * F) + r * F + f0) = o;
            }
        }
    }
}

// ---------------------------------------------------------------------------
extern "C" void kernel_launch(void* const* d_in, const int* in_sizes, int n_in,
                              void* d_out, int out_size) {
    const float* h    = (const float*)d_in[0];
    const float* edge = (const float*)d_in[1];
    const float* W    = (const float*)d_in[2];
    const float* a    = (const float*)d_in[3];
    float* out = (float*)d_out;

    const long long size1 = (long long)N * R * F;   // 1,048,576
    const long long sizeE = (long long)R * N * N;   // 67,108,864

    float* out1 = nullptr;
    float* outE = nullptr;
    if ((long long)out_size >= size1 + sizeE) {
        out1 = out;
        outE = out + size1;
    } else if ((long long)out_size >= sizeE) {
        outE = out;
    } else {
        out1 = out;
    }

    cudaFuncSetAttribute(k_fused, cudaFuncAttributeMaxDynamicSharedMemorySize,
                         SMEM_TOTAL);

    k_wh<<<N, 64>>>(h, W, a);
    k_split<<<N / 64, 256>>>();

    dim3 g2(N / 1024, SEGS, R);
    k_stats_part<<<g2, 256>>>(edge);
    k_stats_final<<<(R * N) / 256, 256>>>();

    dim3 g3(N / TI, R);
    k_fused<<<g3, 256, SMEM_TOTAL>>>(edge, out1, outE);
}

// round 10
// speedup vs baseline: 1.0638x; 1.0297x over previous
#include <cuda_runtime.h>
#include <cuda_bf16.h>
#include <cstdint>

// ---------------------------------------------------------------------------
// GraphAttentionLayer: N=4096, R=4, Fin=256, Fout=64
//   Wh = h@W; Wh1 = Wh@a[:F]; Wh2 = Wh@a[F:]
//   s  = leaky_relu(Wh1_i + Wh2_j, 0.2) * A[r,i,j]   (A<=0 -> masked)
//   e  = softmax over i (axis=1)  -> column-normalized
//   h' = einsum('rij,jf->rif', e, Wh)  -> warp mma.sync bf16x2, 3 chains
//   out = [ elu(h_cat) (N x R*F) | e (R x N x N) ]
//
// R10: exp computed ONCE. k_stats writes unnormalized exp(s) into the e
// output buffer while accumulating column sums; k_fused reads it back,
// scales by 1/l in place, and feeds the MMA. No MUFU in k_fused.
// ---------------------------------------------------------------------------

namespace {
constexpr int N    = 4096;
constexpr int R    = 4;
constexpr int FIN  = 256;
constexpr int F    = 64;
constexpr int SEGS = 32;
constexpr int SEGLEN = N / SEGS;     // 128
constexpr int TI   = 64;             // i-tile
constexpr int TJ   = 64;             // j chunk
constexpr int NC   = N / TJ;         // 64
constexpr float ALPHA = 0.2f;

// smem layout (bytes)
constexpr int B_STRIDE = 144;
constexpr int B_SPLIT  = F * B_STRIDE;        // 9216
constexpr int B_BUF    = 2 * B_SPLIT;         // 18432
constexpr int OFF_B    = 0;                   // 2 buffers
constexpr int A_STRIDE = 144;
constexpr int A_SPLIT  = TI * A_STRIDE;       // 9216
constexpr int OFF_A    = 2 * B_BUF;           // 36864 ; 2 splits
constexpr int SMEM_TOTAL = OFF_A + 2 * A_SPLIT;  // 55296
}

// Scratch (static device globals; no runtime allocation)
__device__ __align__(16) float g_Wh[N * F];                 // 1 MB
__device__ __align__(16) __nv_bfloat16 g_WhT[2][F][N];      // 1 MB
__device__ float g_Wh1[N];
__device__ float g_Wh2[N];
__device__ __align__(16) float g_pl[R * SEGS * N];
__device__ __align__(16) float g_linv[R * N];
// fallback exp buffer (used only if the harness output lacks the e region)
__device__ __align__(16) float g_escr[(size_t)R * N * N];

// ---------------------------------------------------------------------------
// PTX helpers
// ---------------------------------------------------------------------------
__device__ __forceinline__ uint32_t smem_u32(const void* p) {
    return (uint32_t)__cvta_generic_to_shared(p);
}
__device__ __forceinline__ void cp16(uint32_t dst, const void* src) {
    asm volatile("cp.async.cg.shared.global [%0], [%1], 16;" :: "r"(dst), "l"(src));
}
__device__ __forceinline__ void cp_commit() {
    asm volatile("cp.async.commit_group;");
}
template <int NG>
__device__ __forceinline__ void cp_wait() {
    asm volatile("cp.async.wait_group %0;" :: "n"(NG));
}
__device__ __forceinline__ void bar_pair(int id) {
    asm volatile("bar.sync %0, 64;" :: "r"(id) : "memory");
}
__device__ __forceinline__ void ldm4(uint32_t& d0, uint32_t& d1, uint32_t& d2,
                                     uint32_t& d3, uint32_t addr) {
    asm volatile("ldmatrix.sync.aligned.m8n8.x4.shared.b16 {%0,%1,%2,%3}, [%4];"
                 : "=r"(d0), "=r"(d1), "=r"(d2), "=r"(d3) : "r"(addr));
}
__device__ __forceinline__ void mma16816(float* c, const uint32_t* a,
                                         uint32_t b0, uint32_t b1) {
    asm volatile(
        "mma.sync.aligned.m16n8k16.row.col.f32.bf16.bf16.f32 "
        "{%0,%1,%2,%3}, {%4,%5,%6,%7}, {%8,%9}, {%0,%1,%2,%3};"
        : "+f"(c[0]), "+f"(c[1]), "+f"(c[2]), "+f"(c[3])
        : "r"(a[0]), "r"(a[1]), "r"(a[2]), "r"(a[3]), "r"(b0), "r"(b1));
}
__device__ __forceinline__ void sts_v2(uint32_t addr, uint32_t u0, uint32_t u1) {
    asm volatile("st.shared.v2.b32 [%0], {%1, %2};" :: "r"(addr), "r"(u0), "r"(u1));
}

// ---------------------------------------------------------------------------
// Kernel 1: Wh [N,F], Wh1[N], Wh2[N].  grid = N blocks x 64 threads.
// ---------------------------------------------------------------------------
__global__ __launch_bounds__(64) void k_wh(const float* __restrict__ h,
                                           const float* __restrict__ W,
                                           const float* __restrict__ a) {
    __shared__ float hs[FIN];
    __shared__ float red[4];
    const int i = blockIdx.x;
    const int f = threadIdx.x;

    #pragma unroll
    for (int k = f; k < FIN; k += 64) hs[k] = h[(size_t)i * FIN + k];
    __syncthreads();

    float acc = 0.f;
    #pragma unroll 8
    for (int k = 0; k < FIN; k++) acc = fmaf(hs[k], W[k * F + f], acc);
    g_Wh[(size_t)i * F + f] = acc;

    float v1 = acc * a[f];
    float v2 = acc * a[F + f];
    #pragma unroll
    for (int off = 16; off; off >>= 1) {
        v1 += __shfl_down_sync(0xffffffffu, v1, off);
        v2 += __shfl_down_sync(0xffffffffu, v2, off);
    }
    if ((f & 31) == 0) { red[f >> 5] = v1; red[2 + (f >> 5)] = v2; }
    __syncthreads();
    if (f == 0) {
        g_Wh1[i] = red[0] + red[1];
        g_Wh2[i] = red[2] + red[3];
    }
}

// ---------------------------------------------------------------------------
// Kernel 1b: transpose + bf16x2 split of Wh -> g_WhT[s][f][j].
// ---------------------------------------------------------------------------
__global__ __launch_bounds__(256) void k_split() {
    __shared__ float sT[F][64 + 1];
    const int i0 = blockIdx.x * 64;
    const int t = threadIdx.x;

    for (int idx = t; idx < 64 * F; idx += 256) {
        const int i = idx >> 6;
        const int f = idx & 63;
        sT[f][i] = g_Wh[(size_t)(i0 + i) * F + f];
    }
    __syncthreads();
    for (int idx = t; idx < 64 * F; idx += 256) {
        const int f  = idx >> 6;
        const int ii = idx & 63;
        const float w = sT[f][ii];
        const __nv_bfloat16 b0 = __float2bfloat16(w);
        const __nv_bfloat16 b1 = __float2bfloat16(w - __bfloat162float(b0));
        g_WhT[0][f][i0 + ii] = b0;
        g_WhT[1][f][i0 + ii] = b1;
    }
}

// ---------------------------------------------------------------------------
// Kernel 2a: exp(s) -> e-buffer (unnormalized) + partial column sums.
// grid = (N/1024, SEGS, R) = (4, 32, 4) = 512 blocks, 256 threads.
// Thread owns 4 consecutive columns over 128 rows.
// ---------------------------------------------------------------------------
__global__ __launch_bounds__(256) void k_stats(const float* __restrict__ edge,
                                               float* __restrict__ ebuf) {
    __shared__ float swh1[SEGLEN];
    const int t   = threadIdx.x;
    const int j   = blockIdx.x * 1024 + 4 * t;
    const int seg = blockIdx.y;
    const int r   = blockIdx.z;
    const int i0  = seg * SEGLEN;

    if (t < SEGLEN) swh1[t] = g_Wh1[i0 + t];
    __syncthreads();

    const float4 w2 = *(const float4*)(g_Wh2 + j);
    const size_t off0 = (size_t)r * N * N + (size_t)i0 * N + j;
    const float* base = edge + off0;
    float* ebase = ebuf + off0;

    float lx = 0.f, ly = 0.f, lz = 0.f, lw = 0.f;
    #pragma unroll 4
    for (int k = 0; k < SEGLEN; k++) {
        const float4 a = __ldg((const float4*)(base + (size_t)k * N));
        const float xr = swh1[k];
        float x, lr;
        float4 e;
        x = xr + w2.x; lr = fmaxf(x, ALPHA * x);
        e.x = (a.x > 0.f) ? __expf(lr * a.x) : 0.f;
        x = xr + w2.y; lr = fmaxf(x, ALPHA * x);
        e.y = (a.y > 0.f) ? __expf(lr * a.y) : 0.f;
        x = xr + w2.z; lr = fmaxf(x, ALPHA * x);
        e.z = (a.z > 0.f) ? __expf(lr * a.z) : 0.f;
        x = xr + w2.w; lr = fmaxf(x, ALPHA * x);
        e.w = (a.w > 0.f) ? __expf(lr * a.w) : 0.f;
        __stcs((float4*)(ebase + (size_t)k * N), e);
        lx += e.x; ly += e.y; lz += e.z; lw += e.w;
    }
    float4 out;
    out.x = lx; out.y = ly; out.z = lz; out.w = lw;
    *(float4*)(g_pl + ((size_t)r * SEGS + seg) * N + j) = out;
}

// ---------------------------------------------------------------------------
// Kernel 2b: merge -> g_linv.  grid = R*N/256 = 64 blocks x 256 threads.
// ---------------------------------------------------------------------------
__global__ __launch_bounds__(256) void k_stats_final() {
    const int idx = blockIdx.x * 256 + threadIdx.x;   // r*N + j
    const int r = idx >> 12;
    const int j = idx & (N - 1);
    float L = 0.f;
    #pragma unroll
    for (int s = 0; s < SEGS; s++) L += g_pl[((size_t)r * SEGS + s) * N + j];
    g_linv[idx] = 1.f / L;
}

// ---------------------------------------------------------------------------
// Kernel 3 (fused): per (r, 64-row tile), all 64 j-chunks.
// Reads unnormalized exp from ebuf, scales by linv in place (normalized e),
// builds bf16x2 A splits, warp mma m16n8k16 (3 chains), elu epilogue.
// Per chunk: one block barrier (B handoff) + one 64-thr pair barrier (A).
// grid = (N/TI, R) = (64, 4) = 256 blocks, 256 threads, 2 blocks/SM.
// ---------------------------------------------------------------------------
__global__ __launch_bounds__(256, 2) void k_fused(float* __restrict__ ebuf,
                                                  float* __restrict__ out1) {
    extern __shared__ __align__(128) char smc[];
    const uint32_t smb = smem_u32(smc);

    const int t    = threadIdx.x;
    const int wid  = t >> 5;
    const int lane = t & 31;
    const int mg   = wid >> 1;        // 0..3 m-group (16 rows)
    const int nh   = wid & 1;         // 0..1 n-half (32 cols)
    const int cl   = lane & 15;       // col group (4 floats)
    const int rh   = lane >> 4;       // row offset within pair
    const int r    = blockIdx.y;
    const int i0   = blockIdx.x * TI;
    const size_t ebase = (size_t)r * N * N;

    const int trow = 16 * mg + 8 * nh;    // transform row base (8 rows)

    // ldmatrix lane address bases (constant over chunks)
    const uint32_t aBase = smb + OFF_A;
    const uint32_t aLd = aBase +
        (uint32_t)((16 * mg + (lane & 7) + 8 * ((lane >> 3) & 1)) * A_STRIDE +
                   (lane >> 4) * 16);
    const uint32_t bLBase = smb + OFF_B +
        (uint32_t)(((lane & 7) + 8 * (lane >> 4)) * B_STRIDE +
                   ((lane >> 3) & 1) * 16);

    auto issue_cpB = [&](int jc) {
        const int buf = jc & 1;
        const int j0 = jc * TJ;
        const uint32_t bBase = smb + OFF_B + buf * B_BUF;
        #pragma unroll
        for (int g = 0; g < 4; g++) {
            const int idx = g * 256 + t;        // 0..1023
            const int s   = idx >> 9;           // split
            const int rem = idx & 511;
            const int row = rem >> 3;           // f row
            const int c16 = rem & 7;
            cp16(bBase + s * B_SPLIT + (uint32_t)(row * B_STRIDE + c16 * 16),
                 &g_WhT[s][row][j0 + c16 * 8]);
        }
        cp_commit();
    };
    // raw rows: iteration k covers rows trow+2k+rh, cols j0+4*cl..+3
    auto issue_raw = [&](int jc, float4 (&raw)[4]) {
        const int j0 = jc * TJ;
        const float* base = ebuf + ebase + (size_t)(i0 + trow + rh) * N + j0 + 4 * cl;
        #pragma unroll
        for (int k = 0; k < 4; k++)
            raw[k] = __ldg((const float4*)(base + (size_t)(2 * k) * N));
    };

    float c[4][4];
    #pragma unroll
    for (int ng = 0; ng < 4; ng++)
        #pragma unroll
        for (int u = 0; u < 4; u++) c[ng][u] = 0.f;

    auto step = [&](int jc, float4 (&cur)[4], float4 (&nxt)[4],
                    float4& lnvC, float4& lnvN) {
        const int j0 = jc * TJ;
        const bool more = (jc + 1 < NC);
        // issue raw LDGs before the wait point so they overlap the stall
        if (more) {
            issue_raw(jc + 1, nxt);
            lnvN = __ldg((const float4*)(g_linv + r * N + j0 + TJ + 4 * cl));
        }

        cp_wait<0>();          // B(jc) landed (issued last step)
        __syncthreads();       // B(jc) visible; all warps' MMA(jc-1) done
        if (more) issue_cpB(jc + 1);   // overwrites buf (jc-1)&1 — now safe

        // ---- transform: exp -> normalized e (in place) + bf16x2 A splits ----
        #pragma unroll
        for (int k = 0; k < 4; k++) {
            const int row = trow + 2 * k + rh;
            float4 ev;
            ev.x = cur[k].x * lnvC.x;
            ev.y = cur[k].y * lnvC.y;
            ev.z = cur[k].z * lnvC.z;
            ev.w = cur[k].w * lnvC.w;
            __stcs((float4*)(ebuf + ebase + (size_t)(i0 + row) * N + j0 + 4 * cl),
                   ev);

            // bf16x2 splits: cols (4cl, 4cl+1) and (4cl+2, 4cl+3)
            const __nv_bfloat162 h01 = __floats2bfloat162_rn(ev.x, ev.y);
            const __nv_bfloat162 h23 = __floats2bfloat162_rn(ev.z, ev.w);
            const __nv_bfloat162 l01 = __floats2bfloat162_rn(
                ev.x - __bfloat162float(h01.x), ev.y - __bfloat162float(h01.y));
            const __nv_bfloat162 l23 = __floats2bfloat162_rn(
                ev.z - __bfloat162float(h23.x), ev.w - __bfloat162float(h23.y));
            const uint32_t so = (uint32_t)(row * A_STRIDE + cl * 8);
            sts_v2(aBase + so, *(const uint32_t*)&h01, *(const uint32_t*)&h23);
            sts_v2(aBase + A_SPLIT + so, *(const uint32_t*)&l01,
                   *(const uint32_t*)&l23);
        }

        // pair barrier: partner's 8 A-rows visible (64 threads, id = mg+1)
        bar_pair(mg + 1);

        // ---- MMA: 4 k-steps x 2 n16-groups (this warp's half) x 3 chains ----
        const uint32_t bBuf = bLBase + (jc & 1) * B_BUF;
        #pragma unroll
        for (int ks = 0; ks < 4; ks++) {
            uint32_t a0[4], a1[4];
            ldm4(a0[0], a0[1], a0[2], a0[3], aLd + ks * 32);
            ldm4(a1[0], a1[1], a1[2], a1[3], aLd + A_SPLIT + ks * 32);
            #pragma unroll
            for (int u = 0; u < 2; u++) {
                const int ng2 = 2 * nh + u;
                const uint32_t bo = bBuf + (uint32_t)(ng2 * 16 * B_STRIDE + ks * 32);
                uint32_t b00, b01, b02, b03, b10, b11, b12, b13;
                ldm4(b00, b01, b02, b03, bo);
                ldm4(b10, b11, b12, b13, bo + B_SPLIT);
                mma16816(c[2 * u], a0, b00, b01);
                mma16816(c[2 * u], a0, b10, b11);
                mma16816(c[2 * u], a1, b00, b01);
                mma16816(c[2 * u + 1], a0, b02, b03);
                mma16816(c[2 * u + 1], a0, b12, b13);
                mma16816(c[2 * u + 1], a1, b02, b03);
            }
        }
        // no trailing barrier: next step's __syncthreads protects A and B buf

        lnvC = lnvN;
    };

    // ---- pipeline ----
    float4 rawP[4], rawQ[4];
    float4 lnvC, lnvN;
    issue_cpB(0);
    issue_raw(0, rawP);
    lnvC = __ldg((const float4*)(g_linv + r * N + 4 * cl));
    lnvN = lnvC;

    for (int jc = 0; jc < NC; jc += 2) {
        step(jc, rawP, rawQ, lnvC, lnvN);
        step(jc + 1, rawQ, rawP, lnvC, lnvN);
    }

    // ---- epilogue: elu + store out1[i, r*F + f] ----
    if (out1 != nullptr) {
        const int rlo = i0 + 16 * mg + (lane >> 2);
        const int rhi = rlo + 8;
        #pragma unroll
        for (int u = 0; u < 2; u++) {
            const int ng2 = 2 * nh + u;
            #pragma unroll
            for (int v = 0; v < 2; v++) {
                const int f0 = 8 * (2 * ng2 + v) + 2 * (lane & 3);
                const float* cc = c[2 * u + v];
                float2 o;
                o.x = (cc[0] > 0.f) ? cc[0] : expm1f(cc[0]);
                o.y = (cc[1] > 0.f) ? cc[1] : expm1f(cc[1]);
                *(float2*)(out1 + (size_t)rlo * (R * F) + r * F + f0) = o;
                o.x = (cc[2] > 0.f) ? cc[2] : expm1f(cc[2]);
                o.y = (cc[3] > 0.f) ? cc[3] : expm1f(cc[3]);
                *(float2*)(out1 + (size_t)rhi * (R * F) + r * F + f0) = o;
            }
        }
    }
}

// ---------------------------------------------------------------------------
extern "C" void kernel_launch(void* const* d_in, const int* in_sizes, int n_in,
                              void* d_out, int out_size) {
    const float* h    = (const float*)d_in[0];
    const float* edge = (const float*)d_in[1];
    const float* W    = (const float*)d_in[2];
    const float* a    = (const float*)d_in[3];
    float* out = (float*)d_out;

    const long long size1 = (long long)N * R * F;   // 1,048,576
    const long long sizeE = (long long)R * N * N;   // 67,108,864

    float* out1 = nullptr;
    float* outE = nullptr;
    if ((long long)out_size >= size1 + sizeE) {
        out1 = out;
        outE = out + size1;
    } else if ((long long)out_size >= sizeE) {
        outE = out;
    } else {
        out1 = out;
    }

    // exp staging buffer: the e output region if present, else device scratch
    float* ebuf = outE;
    if (ebuf == nullptr) {
        cudaGetSymbolAddress((void**)&ebuf, g_escr);
    }

    cudaFuncSetAttribute(k_fused, cudaFuncAttributeMaxDynamicSharedMemorySize,
                         SMEM_TOTAL);

    k_wh<<<N, 64>>>(h, W, a);
    k_split<<<N / 64, 256>>>();

    dim3 g2(N / 1024, SEGS, R);
    k_stats<<<g2, 256>>>(edge, ebuf);
    k_stats_final<<<(R * N) / 256, 256>>>();

    dim3 g3(N / TI, R);
    k_fused<<<g3, 256, SMEM_TOTAL>>>(ebuf, out1);
}

// round 11
// speedup vs baseline: 1.0815x; 1.0167x over previous
#include <cuda_runtime.h>
#include <cuda_bf16.h>
#include <cstdint>

// ---------------------------------------------------------------------------
// GraphAttentionLayer: N=4096, R=4, Fin=256, Fout=64
//   Wh = h@W; Wh1 = Wh@a[:F]; Wh2 = Wh@a[F:]
//   s  = leaky_relu(Wh1_i + Wh2_j, 0.2) * A[r,i,j]   (A<=0 -> masked)
//   e  = softmax over i (axis=1)  -> column-normalized
//   h' = einsum('rij,jf->rif', e, Wh)  -> warp mma.sync bf16x2, 3 chains
//   out = [ elu(h_cat) (N x R*F) | e (R x N x N) ]
//
// R11: R10 + 3 blocks/SM on k_fused (__launch_bounds__(256,3), lnv loaded
// per-chunk from L1 instead of register double-buffering).
// ---------------------------------------------------------------------------

namespace {
constexpr int N    = 4096;
constexpr int R    = 4;
constexpr int FIN  = 256;
constexpr int F    = 64;
constexpr int SEGS = 32;
constexpr int SEGLEN = N / SEGS;     // 128
constexpr int TI   = 64;             // i-tile
constexpr int TJ   = 64;             // j chunk
constexpr int NC   = N / TJ;         // 64
constexpr float ALPHA = 0.2f;

// smem layout (bytes)
constexpr int B_STRIDE = 144;
constexpr int B_SPLIT  = F * B_STRIDE;        // 9216
constexpr int B_BUF    = 2 * B_SPLIT;         // 18432
constexpr int OFF_B    = 0;                   // 2 buffers
constexpr int A_STRIDE = 144;
constexpr int A_SPLIT  = TI * A_STRIDE;       // 9216
constexpr int OFF_A    = 2 * B_BUF;           // 36864 ; 2 splits
constexpr int SMEM_TOTAL = OFF_A + 2 * A_SPLIT;  // 55296
}

// Scratch (static device globals; no runtime allocation)
__device__ __align__(16) float g_Wh[N * F];                 // 1 MB
__device__ __align__(16) __nv_bfloat16 g_WhT[2][F][N];      // 1 MB
__device__ float g_Wh1[N];
__device__ float g_Wh2[N];
__device__ __align__(16) float g_pl[R * SEGS * N];
__device__ __align__(16) float g_linv[R * N];
// fallback exp buffer (used only if the harness output lacks the e region)
__device__ __align__(16) float g_escr[(size_t)R * N * N];

// ---------------------------------------------------------------------------
// PTX helpers
// ---------------------------------------------------------------------------
__device__ __forceinline__ uint32_t smem_u32(const void* p) {
    return (uint32_t)__cvta_generic_to_shared(p);
}
__device__ __forceinline__ void cp16(uint32_t dst, const void* src) {
    asm volatile("cp.async.cg.shared.global [%0], [%1], 16;" :: "r"(dst), "l"(src));
}
__device__ __forceinline__ void cp_commit() {
    asm volatile("cp.async.commit_group;");
}
template <int NG>
__device__ __forceinline__ void cp_wait() {
    asm volatile("cp.async.wait_group %0;" :: "n"(NG));
}
__device__ __forceinline__ void bar_pair(int id) {
    asm volatile("bar.sync %0, 64;" :: "r"(id) : "memory");
}
__device__ __forceinline__ void ldm4(uint32_t& d0, uint32_t& d1, uint32_t& d2,
                                     uint32_t& d3, uint32_t addr) {
    asm volatile("ldmatrix.sync.aligned.m8n8.x4.shared.b16 {%0,%1,%2,%3}, [%4];"
                 : "=r"(d0), "=r"(d1), "=r"(d2), "=r"(d3) : "r"(addr));
}
__device__ __forceinline__ void mma16816(float* c, const uint32_t* a,
                                         uint32_t b0, uint32_t b1) {
    asm volatile(
        "mma.sync.aligned.m16n8k16.row.col.f32.bf16.bf16.f32 "
        "{%0,%1,%2,%3}, {%4,%5,%6,%7}, {%8,%9}, {%0,%1,%2,%3};"
        : "+f"(c[0]), "+f"(c[1]), "+f"(c[2]), "+f"(c[3])
        : "r"(a[0]), "r"(a[1]), "r"(a[2]), "r"(a[3]), "r"(b0), "r"(b1));
}
__device__ __forceinline__ void sts_v2(uint32_t addr, uint32_t u0, uint32_t u1) {
    asm volatile("st.shared.v2.b32 [%0], {%1, %2};" :: "r"(addr), "r"(u0), "r"(u1));
}

// ---------------------------------------------------------------------------
// Kernel 1: Wh [N,F], Wh1[N], Wh2[N].  grid = N blocks x 64 threads.
// ---------------------------------------------------------------------------
__global__ __launch_bounds__(64) void k_wh(const float* __restrict__ h,
                                           const float* __restrict__ W,
                                           const float* __restrict__ a) {
    __shared__ float hs[FIN];
    __shared__ float red[4];
    const int i = blockIdx.x;
    const int f = threadIdx.x;

    #pragma unroll
    for (int k = f; k < FIN; k += 64) hs[k] = h[(size_t)i * FIN + k];
    __syncthreads();

    float acc = 0.f;
    #pragma unroll 8
    for (int k = 0; k < FIN; k++) acc = fmaf(hs[k], W[k * F + f], acc);
    g_Wh[(size_t)i * F + f] = acc;

    float v1 = acc * a[f];
    float v2 = acc * a[F + f];
    #pragma unroll
    for (int off = 16; off; off >>= 1) {
        v1 += __shfl_down_sync(0xffffffffu, v1, off);
        v2 += __shfl_down_sync(0xffffffffu, v2, off);
    }
    if ((f & 31) == 0) { red[f >> 5] = v1; red[2 + (f >> 5)] = v2; }
    __syncthreads();
    if (f == 0) {
        g_Wh1[i] = red[0] + red[1];
        g_Wh2[i] = red[2] + red[3];
    }
}

// ---------------------------------------------------------------------------
// Kernel 1b: transpose + bf16x2 split of Wh -> g_WhT[s][f][j].
// ---------------------------------------------------------------------------
__global__ __launch_bounds__(256) void k_split() {
    __shared__ float sT[F][64 + 1];
    const int i0 = blockIdx.x * 64;
    const int t = threadIdx.x;

    for (int idx = t; idx < 64 * F; idx += 256) {
        const int i = idx >> 6;
        const int f = idx & 63;
        sT[f][i] = g_Wh[(size_t)(i0 + i) * F + f];
    }
    __syncthreads();
    for (int idx = t; idx < 64 * F; idx += 256) {
        const int f  = idx >> 6;
        const int ii = idx & 63;
        const float w = sT[f][ii];
        const __nv_bfloat16 b0 = __float2bfloat16(w);
        const __nv_bfloat16 b1 = __float2bfloat16(w - __bfloat162float(b0));
        g_WhT[0][f][i0 + ii] = b0;
        g_WhT[1][f][i0 + ii] = b1;
    }
}

// ---------------------------------------------------------------------------
// Kernel 2a: exp(s) -> e-buffer (unnormalized) + partial column sums.
// grid = (N/1024, SEGS, R) = (4, 32, 4) = 512 blocks, 256 threads.
// ---------------------------------------------------------------------------
__global__ __launch_bounds__(256) void k_stats(const float* __restrict__ edge,
                                               float* __restrict__ ebuf) {
    __shared__ float swh1[SEGLEN];
    const int t   = threadIdx.x;
    const int j   = blockIdx.x * 1024 + 4 * t;
    const int seg = blockIdx.y;
    const int r   = blockIdx.z;
    const int i0  = seg * SEGLEN;

    if (t < SEGLEN) swh1[t] = g_Wh1[i0 + t];
    __syncthreads();

    const float4 w2 = *(const float4*)(g_Wh2 + j);
    const size_t off0 = (size_t)r * N * N + (size_t)i0 * N + j;
    const float* base = edge + off0;
    float* ebase = ebuf + off0;

    float lx = 0.f, ly = 0.f, lz = 0.f, lw = 0.f;
    #pragma unroll 4
    for (int k = 0; k < SEGLEN; k++) {
        const float4 a = __ldg((const float4*)(base + (size_t)k * N));
        const float xr = swh1[k];
        float x, lr;
        float4 e;
        x = xr + w2.x; lr = fmaxf(x, ALPHA * x);
        e.x = (a.x > 0.f) ? __expf(lr * a.x) : 0.f;
        x = xr + w2.y; lr = fmaxf(x, ALPHA * x);
        e.y = (a.y > 0.f) ? __expf(lr * a.y) : 0.f;
        x = xr + w2.z; lr = fmaxf(x, ALPHA * x);
        e.z = (a.z > 0.f) ? __expf(lr * a.z) : 0.f;
        x = xr + w2.w; lr = fmaxf(x, ALPHA * x);
        e.w = (a.w > 0.f) ? __expf(lr * a.w) : 0.f;
        __stcs((float4*)(ebase + (size_t)k * N), e);
        lx += e.x; ly += e.y; lz += e.z; lw += e.w;
    }
    float4 out;
    out.x = lx; out.y = ly; out.z = lz; out.w = lw;
    *(float4*)(g_pl + ((size_t)r * SEGS + seg) * N + j) = out;
}

// ---------------------------------------------------------------------------
// Kernel 2b: merge -> g_linv.  grid = R*N/256 = 64 blocks x 256 threads.
// ---------------------------------------------------------------------------
__global__ __launch_bounds__(256) void k_stats_final() {
    const int idx = blockIdx.x * 256 + threadIdx.x;   // r*N + j
    const int r = idx >> 12;
    const int j = idx & (N - 1);
    float L = 0.f;
    #pragma unroll
    for (int s = 0; s < SEGS; s++) L += g_pl[((size_t)r * SEGS + s) * N + j];
    g_linv[idx] = 1.f / L;
}

// ---------------------------------------------------------------------------
// Kernel 3 (fused): per (r, 64-row tile), all 64 j-chunks.
// Reads unnormalized exp from ebuf, scales by linv in place (normalized e),
// builds bf16x2 A splits, warp mma m16n8k16 (3 chains), elu epilogue.
// Per chunk: one block barrier (B handoff) + one 64-thr pair barrier (A).
// grid = (N/TI, R) = (64, 4) = 256 blocks, 256 threads, 3 blocks/SM.
// ---------------------------------------------------------------------------
__global__ __launch_bounds__(256, 3) void k_fused(float* __restrict__ ebuf,
                                                  float* __restrict__ out1) {
    extern __shared__ __align__(128) char smc[];
    const uint32_t smb = smem_u32(smc);

    const int t    = threadIdx.x;
    const int wid  = t >> 5;
    const int lane = t & 31;
    const int mg   = wid >> 1;        // 0..3 m-group (16 rows)
    const int nh   = wid & 1;         // 0..1 n-half (32 cols)
    const int cl   = lane & 15;       // col group (4 floats)
    const int rh   = lane >> 4;       // row offset within pair
    const int r    = blockIdx.y;
    const int i0   = blockIdx.x * TI;
    const size_t ebase = (size_t)r * N * N;

    const int trow = 16 * mg + 8 * nh;    // transform row base (8 rows)

    // ldmatrix lane address bases (constant over chunks)
    const uint32_t aBase = smb + OFF_A;
    const uint32_t aLd = aBase +
        (uint32_t)((16 * mg + (lane & 7) + 8 * ((lane >> 3) & 1)) * A_STRIDE +
                   (lane >> 4) * 16);
    const uint32_t bLBase = smb + OFF_B +
        (uint32_t)(((lane & 7) + 8 * (lane >> 4)) * B_STRIDE +
                   ((lane >> 3) & 1) * 16);

    auto issue_cpB = [&](int jc) {
        const int buf = jc & 1;
        const int j0 = jc * TJ;
        const uint32_t bBase = smb + OFF_B + buf * B_BUF;
        #pragma unroll
        for (int g = 0; g < 4; g++) {
            const int idx = g * 256 + t;        // 0..1023
            const int s   = idx >> 9;           // split
            const int rem = idx & 511;
            const int row = rem >> 3;           // f row
            const int c16 = rem & 7;
            cp16(bBase + s * B_SPLIT + (uint32_t)(row * B_STRIDE + c16 * 16),
                 &g_WhT[s][row][j0 + c16 * 8]);
        }
        cp_commit();
    };
    // raw rows: iteration k covers rows trow+2k+rh, cols j0+4*cl..+3
    auto issue_raw = [&](int jc, float4 (&raw)[4]) {
        const int j0 = jc * TJ;
        const float* base = ebuf + ebase + (size_t)(i0 + trow + rh) * N + j0 + 4 * cl;
        #pragma unroll
        for (int k = 0; k < 4; k++)
            raw[k] = __ldg((const float4*)(base + (size_t)(2 * k) * N));
    };

    float c[4][4];
    #pragma unroll
    for (int ng = 0; ng < 4; ng++)
        #pragma unroll
        for (int u = 0; u < 4; u++) c[ng][u] = 0.f;

    auto step = [&](int jc, float4 (&cur)[4], float4 (&nxt)[4]) {
        const int j0 = jc * TJ;
        const bool more = (jc + 1 < NC);
        // issue raw LDGs before the wait point so they overlap the stall
        if (more) issue_raw(jc + 1, nxt);

        // linv slice is L1-resident (16 KB per r); load per chunk
        const float4 lnv = __ldg((const float4*)(g_linv + r * N + j0 + 4 * cl));

        cp_wait<0>();          // B(jc) landed (issued last step)
        __syncthreads();       // B(jc) visible; all warps' MMA(jc-1) done
        if (more) issue_cpB(jc + 1);   // overwrites buf (jc-1)&1 — now safe

        // ---- transform: exp -> normalized e (in place) + bf16x2 A splits ----
        #pragma unroll
        for (int k = 0; k < 4; k++) {
            const int row = trow + 2 * k + rh;
            float4 ev;
            ev.x = cur[k].x * lnv.x;
            ev.y = cur[k].y * lnv.y;
            ev.z = cur[k].z * lnv.z;
            ev.w = cur[k].w * lnv.w;
            __stcs((float4*)(ebuf + ebase + (size_t)(i0 + row) * N + j0 + 4 * cl),
                   ev);

            // bf16x2 splits: cols (4cl, 4cl+1) and (4cl+2, 4cl+3)
            const __nv_bfloat162 h01 = __floats2bfloat162_rn(ev.x, ev.y);
            const __nv_bfloat162 h23 = __floats2bfloat162_rn(ev.z, ev.w);
            const __nv_bfloat162 l01 = __floats2bfloat162_rn(
                ev.x - __bfloat162float(h01.x), ev.y - __bfloat162float(h01.y));
            const __nv_bfloat162 l23 = __floats2bfloat162_rn(
                ev.z - __bfloat162float(h23.x), ev.w - __bfloat162float(h23.y));
            const uint32_t so = (uint32_t)(row * A_STRIDE + cl * 8);
            sts_v2(aBase + so, *(const uint32_t*)&h01, *(const uint32_t*)&h23);
            sts_v2(aBase + A_SPLIT + so, *(const uint32_t*)&l01,
                   *(const uint32_t*)&l23);
        }

        // pair barrier: partner's 8 A-rows visible (64 threads, id = mg+1)
        bar_pair(mg + 1);

        // ---- MMA: 4 k-steps x 2 n16-groups (this warp's half) x 3 chains ----
        const uint32_t bBuf = bLBase + (jc & 1) * B_BUF;
        #pragma unroll
        for (int ks = 0; ks < 4; ks++) {
            uint32_t a0[4], a1[4];
            ldm4(a0[0], a0[1], a0[2], a0[3], aLd + ks * 32);
            ldm4(a1[0], a1[1], a1[2], a1[3], aLd + A_SPLIT + ks * 32);
            #pragma unroll
            for (int u = 0; u < 2; u++) {
                const int ng2 = 2 * nh + u;
                const uint32_t bo = bBuf + (uint32_t)(ng2 * 16 * B_STRIDE + ks * 32);
                uint32_t b00, b01, b02, b03, b10, b11, b12, b13;
                ldm4(b00, b01, b02, b03, bo);
                ldm4(b10, b11, b12, b13, bo + B_SPLIT);
                mma16816(c[2 * u], a0, b00, b01);
                mma16816(c[2 * u], a0, b10, b11);
                mma16816(c[2 * u], a1, b00, b01);
                mma16816(c[2 * u + 1], a0, b02, b03);
                mma16816(c[2 * u + 1], a0, b12, b13);
                mma16816(c[2 * u + 1], a1, b02, b03);
            }
        }
        // no trailing barrier: next step's __syncthreads protects A and B buf
    };

    // ---- pipeline ----
    float4 rawP[4], rawQ[4];
    issue_cpB(0);
    issue_raw(0, rawP);

    for (int jc = 0; jc < NC; jc += 2) {
        step(jc, rawP, rawQ);
        step(jc + 1, rawQ, rawP);
    }

    // ---- epilogue: elu + store out1[i, r*F + f] ----
    if (out1 != nullptr) {
        const int rlo = i0 + 16 * mg + (lane >> 2);
        const int rhi = rlo + 8;
        #pragma unroll
        for (int u = 0; u < 2; u++) {
            const int ng2 = 2 * nh + u;
            #pragma unroll
            for (int v = 0; v < 2; v++) {
                const int f0 = 8 * (2 * ng2 + v) + 2 * (lane & 3);
                const float* cc = c[2 * u + v];
                float2 o;
                o.x = (cc[0] > 0.f) ? cc[0] : expm1f(cc[0]);
                o.y = (cc[1] > 0.f) ? cc[1] : expm1f(cc[1]);
                *(float2*)(out1 + (size_t)rlo * (R * F) + r * F + f0) = o;
                o.x = (cc[2] > 0.f) ? cc[2] : expm1f(cc[2]);
                o.y = (cc[3] > 0.f) ? cc[3] : expm1f(cc[3]);
                *(float2*)(out1 + (size_t)rhi * (R * F) + r * F + f0) = o;
            }
        }
    }
}

// ---------------------------------------------------------------------------
extern "C" void kernel_launch(void* const* d_in, const int* in_sizes, int n_in,
                              void* d_out, int out_size) {
    const float* h    = (const float*)d_in[0];
    const float* edge = (const float*)d_in[1];
    const float* W    = (const float*)d_in[2];
    const float* a    = (const float*)d_in[3];
    float* out = (float*)d_out;

    const long long size1 = (long long)N * R * F;   // 1,048,576
    const long long sizeE = (long long)R * N * N;   // 67,108,864

    float* out1 = nullptr;
    float* outE = nullptr;
    if ((long long)out_size >= size1 + sizeE) {
        out1 = out;
        outE = out + size1;
    } else if ((long long)out_size >= sizeE) {
        outE = out;
    } else {
        out1 = out;
    }

    // exp staging buffer: the e output region if present, else device scratch
    float* ebuf = outE;
    if (ebuf == nullptr) {
        cudaGetSymbolAddress((void**)&ebuf, g_escr);
    }

    cudaFuncSetAttribute(k_fused, cudaFuncAttributeMaxDynamicSharedMemorySize,
                         SMEM_TOTAL);

    k_wh<<<N, 64>>>(h, W, a);
    k_split<<<N / 64, 256>>>();

    dim3 g2(N / 1024, SEGS, R);
    k_stats<<<g2, 256>>>(edge, ebuf);
    k_stats_final<<<(R * N) / 256, 256>>>();

    dim3 g3(N / TI, R);
    k_fused<<<g3, 256, SMEM_TOTAL>>>(ebuf, out1);
}